// round 10
// baseline (speedup 1.0000x reference)
#include <cuda_runtime.h>
#include <cuda_bf16.h>
#include <cstdint>
#include <cstddef>

#define K_CB   2048
#define D_DIM  512
#define B_DIM  16
#define N_DIM  8192
#define M_ROWS (B_DIM * N_DIM)
#define MARGIN 1.0f

// -------- device scratch: hi bf16 planes only, packed in dim-pairs ----------
__device__ uint32_t g_Ah[(size_t)M_ROWS * 256];
__device__ uint32_t g_Bh[(size_t)K_CB * 256];
__device__ float    g_e2[K_CB];
__device__ int      g_ind[M_ROWS];
__device__ int      g_lightm[M_ROWS];
__device__ int      g_cand[(size_t)M_ROWS * 4];
__device__ int      g_fullm[M_ROWS];
__device__ int      g_nlight;
__device__ int      g_nfull;

// -------- helpers --------
__device__ __forceinline__ uint32_t smem_u32(const void* p) {
    uint32_t a;
    asm("{ .reg .u64 t; cvta.to.shared.u64 t, %1; cvt.u32.u64 %0, t; }" : "=r"(a) : "l"(p));
    return a;
}
#define CP_A16(s, g) \
    asm volatile("cp.async.cg.shared.global [%0], [%1], 16;" :: "r"(s), "l"(g) : "memory")
#define CP_COMMIT() asm volatile("cp.async.commit_group;" ::: "memory")
#define CP_WAIT(n)  asm volatile("cp.async.wait_group %0;" :: "n"(n) : "memory")

__device__ __forceinline__ void ldsm4(uint32_t* r, uint32_t addr) {
    asm volatile("ldmatrix.sync.aligned.m8n8.x4.shared.b16 {%0,%1,%2,%3}, [%4];"
                 : "=r"(r[0]), "=r"(r[1]), "=r"(r[2]), "=r"(r[3]) : "r"(addr));
}
__device__ __forceinline__ void mma16816(float* c, const uint32_t* a, const uint32_t* b) {
    asm volatile("mma.sync.aligned.m16n8k16.row.col.f32.bf16.bf16.f32 "
                 "{%0,%1,%2,%3}, {%4,%5,%6,%7}, {%8,%9}, {%0,%1,%2,%3};"
                 : "+f"(c[0]), "+f"(c[1]), "+f"(c[2]), "+f"(c[3])
                 : "r"(a[0]), "r"(a[1]), "r"(a[2]), "r"(a[3]), "r"(b[0]), "r"(b[1]));
}
__device__ __forceinline__ uint32_t bf16hi(float v) {
    return (uint32_t)__bfloat16_as_ushort(__float2bfloat16(v));
}

// -------- prep: codebook hi plane + e2 --------
__global__ __launch_bounds__(128) void prep_embed_kernel(const float* __restrict__ embed) {
    int k = blockIdx.x;
    const float* row = embed + (size_t)k * D_DIM;
    uint32_t* bh = g_Bh + (size_t)k * 256;
    float s = 0.f;
    for (int j = threadIdx.x; j < 256; j += 128) {
        float v0 = row[2 * j], v1 = row[2 * j + 1];
        s += v0 * v0 + v1 * v1;
        bh[j] = bf16hi(v0) | (bf16hi(v1) << 16);
    }
    #pragma unroll
    for (int o = 16; o > 0; o >>= 1) s += __shfl_down_sync(0xffffffffu, s, o);
    __shared__ float ws[4];
    if ((threadIdx.x & 31) == 0) ws[threadIdx.x >> 5] = s;
    __syncthreads();
    if (threadIdx.x == 0) g_e2[k] = ws[0] + ws[1] + ws[2] + ws[3];
    if (blockIdx.x == 0 && threadIdx.x == 0) { g_nlight = 0; g_nfull = 0; }
}

// -------- prep: x[B,D,N] -> row-major hi plane (transpose through smem) -----
__global__ __launch_bounds__(256) void prep_x_kernel(const float* __restrict__ x) {
    __shared__ uint16_t t[64][66];
    int b = blockIdx.y, n0 = blockIdx.x * 64;
    const float* xb = x + (size_t)b * D_DIM * N_DIM + n0;
    for (int dc = 0; dc < 8; dc++) {
        __syncthreads();
        #pragma unroll
        for (int l = 0; l < 16; l++) {
            int i = threadIdx.x + l * 256;
            int dd = i >> 6, nn = i & 63;
            t[dd][nn] = (uint16_t)bf16hi(xb[(size_t)(dc * 64 + dd) * N_DIM + nn]);
        }
        __syncthreads();
        #pragma unroll
        for (int l = 0; l < 8; l++) {
            int i = threadIdx.x + l * 256;
            int nn = i >> 5, jj = i & 31;
            uint32_t p = (uint32_t)t[2 * jj][nn] | ((uint32_t)t[2 * jj + 1][nn] << 16);
            g_Ah[(size_t)(b * N_DIM + n0 + nn) * 256 + dc * 32 + jj] = p;
        }
    }
}

// -------- smem: 3-stage ring, each stage = A chunk (16KB) + B chunk (16KB) --
#define STAGE_BYTES 32768
#define SM_DIST (3 * STAGE_BYTES)   // 98304

// one combined chunk load: A kb = c&7 for this block, B chunk c (nt = c>>3)
__device__ __forceinline__ void load_chunk(uint32_t dst, const uint4* Ag,
                                           const uint4* Bg, int c, int tid) {
    const uint4* Bn = Bg + (size_t)(c >> 3) * 8192;
    int kb = c & 7;
    #pragma unroll
    for (int l = 0; l < 4; l++) {
        int i = tid + l * 256;
        int row = i >> 3, ch = i & 7;
        uint32_t soff = (uint32_t)row * 128 + (uint32_t)((ch ^ (row & 7)) << 4);
        size_t goff = (size_t)row * 64 + kb * 8 + ch;
        CP_A16(dst + soff,         Ag + goff);
        CP_A16(dst + 16384 + soff, Bn + goff);
    }
}

// -------- warp-tile compute: 32x64 per warp, 64 dims/chunk, hi x hi ---------
__device__ __forceinline__ void compute_stage(uint32_t sA, uint32_t sB, int lane,
                                              int wm, int wn, float acc[2][8][4]) {
    #pragma unroll
    for (int kk = 0; kk < 4; kk++) {
        uint32_t ah[2][4];
        #pragma unroll
        for (int i = 0; i < 2; i++) {
            int r = wm * 32 + i * 16 + (lane & 15);
            int c = (kk * 2 + (lane >> 4)) ^ (r & 7);
            ldsm4(ah[i], sA + r * 128 + c * 16);
        }
        #pragma unroll
        for (int j16 = 0; j16 < 4; j16++) {
            int n = wn * 64 + j16 * 16 + (lane & 7) + ((lane >> 4) << 3);
            int c = (kk * 2 + ((lane >> 3) & 1)) ^ (n & 7);
            uint32_t bh[4];
            ldsm4(bh, sB + n * 128 + c * 16);
            #pragma unroll
            for (int i = 0; i < 2; i++) {
                mma16816(acc[i][j16 * 2 + 0], ah[i], bh + 0);
                mma16816(acc[i][j16 * 2 + 1], ah[i], bh + 2);
            }
        }
    }
}

#define INS3(r, s, k) do {                                                        \
    if ((s) > v1[r]) { v3[r] = v2[r]; v2[r] = v1[r]; i2[r] = i1[r];               \
                       v1[r] = (s); i1[r] = (k); }                                \
    else if ((s) > v2[r]) { v3[r] = v2[r]; v2[r] = (s); i2[r] = (k); }            \
    else if ((s) > v3[r]) { v3[r] = (s); }                                        \
} while (0)

// -------- main dist + argmax/classify kernel --------
__global__ void __launch_bounds__(256, 2) vq_dist_kernel(float* __restrict__ out_ind_f) {
    extern __shared__ char smem[];
    uint32_t sb = smem_u32(smem);
    const int tid = threadIdx.x, lane = tid & 31, wid = tid >> 5;
    const int wm = wid & 3, wn = wid >> 2;
    const int m0 = blockIdx.x * 128;
    const uint4* Ag = (const uint4*)(g_Ah + (size_t)m0 * 256);
    const uint4* Bg = (const uint4*)g_Bh;

    // prologue: first two chunks in flight
    load_chunk(sb + 0 * STAGE_BYTES, Ag, Bg, 0, tid);
    CP_COMMIT();
    load_chunk(sb + 1 * STAGE_BYTES, Ag, Bg, 1, tid);
    CP_COMMIT();
    int cload = 2;

    float v1[4], v2[4], v3[4];
    int   i1[4], i2[4];
    #pragma unroll
    for (int r = 0; r < 4; r++) {
        v1[r] = v2[r] = v3[r] = -3.0e38f;
        i1[r] = i2[r] = 0;
    }

    for (int nt = 0; nt < 16; nt++) {
        float acc[2][8][4];
        #pragma unroll
        for (int i = 0; i < 2; i++)
            #pragma unroll
            for (int j = 0; j < 8; j++)
                #pragma unroll
                for (int q = 0; q < 4; q++) acc[i][j][q] = 0.f;

        for (int kb = 0; kb < 8; kb++) {
            int c = nt * 8 + kb;
            if (c == 127) { CP_WAIT(0); } else { CP_WAIT(1); }
            __syncthreads();
            uint32_t slot = sb + (c % 3) * STAGE_BYTES;
            compute_stage(slot, slot + 16384, lane, wm, wn, acc);
            if (cload < 128) {
                load_chunk(sb + (cload % 3) * STAGE_BYTES, Ag, Bg, cload, tid);
                CP_COMMIT();
                cload++;
            }
        }

        #pragma unroll
        for (int j = 0; j < 8; j++) {
            int kb_ = nt * 128 + wn * 64 + j * 8 + (lane & 3) * 2;
            float e2a = g_e2[kb_], e2b = g_e2[kb_ + 1];
            #pragma unroll
            for (int i = 0; i < 2; i++) {
                float s0 = 2.f * acc[i][j][0] - e2a;
                float s1 = 2.f * acc[i][j][1] - e2b;
                float s2 = 2.f * acc[i][j][2] - e2a;
                float s3 = 2.f * acc[i][j][3] - e2b;
                int r0 = i * 2, r1 = i * 2 + 1;
                INS3(r0, s0, kb_);
                INS3(r0, s1, kb_ + 1);
                INS3(r1, s2, kb_);
                INS3(r1, s3, kb_ + 1);
            }
        }
    }

    // ---- per-row merge over 8 sources, classify row ----
    float* sV = (float*)smem;                   // [128][8][3]
    int*   sI = (int*)(smem + 128 * 8 * 3 * 4); // [128][8][2]
    __syncthreads();
    #pragma unroll
    for (int r = 0; r < 4; r++) {
        int row = wm * 32 + (r >> 1) * 16 + (r & 1) * 8 + (lane >> 2);
        int src = wn * 4 + (lane & 3);
        float* v = sV + (row * 8 + src) * 3;
        v[0] = v1[r]; v[1] = v2[r]; v[2] = v3[r];
        int* ii = sI + (row * 8 + src) * 2;
        ii[0] = i1[r]; ii[1] = i2[r];
    }
    __syncthreads();
    if (tid < 128) {
        float b1 = -3.0e38f; int bi1 = 0x7fffffff;
        #pragma unroll
        for (int s = 0; s < 8; s++) {
            float v = sV[(tid * 8 + s) * 3];
            int   i = sI[(tid * 8 + s) * 2];
            if (v > b1 || (v == b1 && i < bi1)) { b1 = v; bi1 = i; }
        }
        float thr = b1 - MARGIN;
        int cand[4]; int nc = 0; bool overflow = false;
        #pragma unroll
        for (int s = 0; s < 8; s++) {
            float va = sV[(tid * 8 + s) * 3 + 0];
            float vb = sV[(tid * 8 + s) * 3 + 1];
            float vc = sV[(tid * 8 + s) * 3 + 2];
            int ia = sI[(tid * 8 + s) * 2 + 0];
            int ib = sI[(tid * 8 + s) * 2 + 1];
            if (va >= thr) { if (nc < 4) cand[nc] = ia; nc++; }
            if (vb >= thr) { if (nc < 4) cand[nc] = ib; nc++; }
            if (vc >= thr) overflow = true;
        }
        int m = m0 + tid;
        if (!overflow && nc <= 1) {
            g_ind[m] = bi1;
            out_ind_f[m] = (float)bi1;
        } else if (!overflow && nc <= 4) {
            int slot = atomicAdd(&g_nlight, 1);
            g_lightm[slot] = m;
            #pragma unroll
            for (int c = 0; c < 4; c++) g_cand[(size_t)slot * 4 + c] = (c < nc) ? cand[c] : -1;
        } else {
            int slot = atomicAdd(&g_nfull, 1);
            g_fullm[slot] = m;
        }
    }
}

// -------- light fallback: exact rescore of <=4 candidates, WARP per row -----
__global__ __launch_bounds__(256) void light_kernel(const float* __restrict__ x,
                                                    const float* __restrict__ embed,
                                                    float* __restrict__ out_ind_f) {
    const int nl = g_nlight;
    const int lane = threadIdx.x & 31;
    const int wglob = blockIdx.x * 8 + (threadIdx.x >> 5);
    for (int s = wglob; s < nl; s += gridDim.x * 8) {
        int m = g_lightm[s];
        int b = m >> 13, n = m & (N_DIM - 1);
        const float* xb = x + (size_t)b * D_DIM * N_DIM + n;
        float xr[16];
        #pragma unroll
        for (int j = 0; j < 16; j++)
            xr[j] = xb[(size_t)(lane + 32 * j) * N_DIM];
        float best = -3.0e38f; int bi = 0x7fffffff;
        #pragma unroll
        for (int c = 0; c < 4; c++) {
            int k = g_cand[(size_t)s * 4 + c];
            if (k < 0) break;
            const float* e = embed + (size_t)k * D_DIM;
            float a = 0.f;
            #pragma unroll
            for (int j = 0; j < 16; j++)
                a += xr[j] * e[lane + 32 * j];
            #pragma unroll
            for (int o = 16; o > 0; o >>= 1)
                a += __shfl_xor_sync(0xffffffffu, a, o);
            float sc = 2.f * a - g_e2[k];
            if (sc > best || (sc == best && k < bi)) { best = sc; bi = k; }
        }
        if (lane == 0) { g_ind[m] = bi; out_ind_f[m] = (float)bi; }
    }
}

// -------- full fallback: exact scan of all codewords (rare) --------
__global__ __launch_bounds__(256) void full_kernel(const float* __restrict__ x,
                                                   const float* __restrict__ embed,
                                                   float* __restrict__ out_ind_f) {
    __shared__ float xr[D_DIM];
    __shared__ float bv[256];
    __shared__ int   bI[256];
    int nf = g_nfull;
    for (int f = blockIdx.x; f < nf; f += gridDim.x) {
        int m = g_fullm[f];
        int b = m >> 13, n = m & (N_DIM - 1);
        __syncthreads();
        for (int d = threadIdx.x; d < D_DIM; d += 256)
            xr[d] = x[(size_t)b * D_DIM * N_DIM + (size_t)d * N_DIM + n];
        __syncthreads();
        float best = -3.0e38f; int bi = 0x7fffffff;
        for (int c = 0; c < 8; c++) {
            int k = threadIdx.x + c * 256;
            const float4* er = (const float4*)(embed + (size_t)k * D_DIM);
            float s0 = 0.f, s1 = 0.f, s2 = 0.f, s3 = 0.f;
            #pragma unroll 8
            for (int j = 0; j < 128; j++) {
                float4 e = er[j];
                s0 += xr[4 * j + 0] * e.x;
                s1 += xr[4 * j + 1] * e.y;
                s2 += xr[4 * j + 2] * e.z;
                s3 += xr[4 * j + 3] * e.w;
            }
            float sc = 2.f * ((s0 + s1) + (s2 + s3)) - g_e2[k];
            if (sc > best || (sc == best && k < bi)) { best = sc; bi = k; }
        }
        bv[threadIdx.x] = best; bI[threadIdx.x] = bi;
        __syncthreads();
        for (int o = 128; o > 0; o >>= 1) {
            if (threadIdx.x < o) {
                float ov = bv[threadIdx.x + o]; int oi = bI[threadIdx.x + o];
                if (ov > bv[threadIdx.x] || (ov == bv[threadIdx.x] && oi < bI[threadIdx.x])) {
                    bv[threadIdx.x] = ov; bI[threadIdx.x] = oi;
                }
            }
            __syncthreads();
        }
        if (threadIdx.x == 0) { g_ind[m] = bI[0]; out_ind_f[m] = (float)bI[0]; }
    }
}

// -------- gather: out[b,d,n] = embed[ind[b,n], d] --------
__global__ __launch_bounds__(256) void gather_kernel(const float* __restrict__ embed,
                                                     float* __restrict__ out) {
    extern __shared__ float tile[];
    __shared__ int inds[32];
    const int bb = blockIdx.y;
    const int n0 = blockIdx.x * 32;
    if (threadIdx.x < 32) inds[threadIdx.x] = g_ind[bb * N_DIM + n0 + threadIdx.x];
    __syncthreads();
    for (int i = threadIdx.x; i < 32 * D_DIM; i += 256) {
        int n = i >> 9, d = i & (D_DIM - 1);
        tile[n * 513 + d] = embed[(size_t)inds[n] * D_DIM + d];
    }
    __syncthreads();
    float* obase = out + (size_t)bb * D_DIM * N_DIM + n0;
    for (int i = threadIdx.x; i < 32 * D_DIM; i += 256) {
        int n = i & 31, d = i >> 5;
        obase[(size_t)d * N_DIM + n] = tile[n * 513 + d];
    }
}

// ---------------------------------------------------------------------------
extern "C" void kernel_launch(void* const* d_in, const int* in_sizes, int n_in,
                              void* d_out, int out_size) {
    const float* x     = (const float*)d_in[0];
    const float* embed = (const float*)d_in[1];
    float* out   = (float*)d_out;
    float* out_q = out;
    float* out_i = out + (size_t)B_DIM * D_DIM * N_DIM;
    (void)in_sizes; (void)n_in; (void)out_size;

    static const int gather_smem = 32 * 513 * (int)sizeof(float);
    cudaFuncSetAttribute(gather_kernel, cudaFuncAttributeMaxDynamicSharedMemorySize, gather_smem);
    cudaFuncSetAttribute(vq_dist_kernel, cudaFuncAttributeMaxDynamicSharedMemorySize, SM_DIST);

    prep_embed_kernel<<<K_CB, 128>>>(embed);
    prep_x_kernel<<<dim3(N_DIM / 64, B_DIM), 256>>>(x);
    vq_dist_kernel<<<M_ROWS / 128, 256, SM_DIST>>>(out_i);
    light_kernel<<<1024, 256>>>(x, embed, out_i);
    full_kernel<<<128, 256>>>(x, embed, out_i);
    gather_kernel<<<dim3(N_DIM / 32, B_DIM), 256, gather_smem>>>(embed, out_q);
}